// round 2
// baseline (speedup 1.0000x reference)
#include <cuda_runtime.h>
#include <math.h>

#define KK   256
#define CC   256
#define BB   4
#define HH   112
#define WW   112
#define OSZ  14
#define PP   196      // OSZ*OSZ
#define HWSZ (HH*WW)
#define OC64 64
#define G16  16

// ---------------- scratch (device globals; no allocations allowed) -------------
__device__ float g_semt[BB*HWSZ*CC];      // semantic in NHWC
__device__ float g_roi_sem[KK*CC*PP];     // raw roi-aligned semantic  [k][c][p]
__device__ float g_act_sem[KK*CC*PP];     // bn_relu(roi_sem)
__device__ float g_act_fpn[KK*CC*PP];     // bn_relu(roi_feature)
__device__ float g_a[KK*OC64*PP];         // conv_sem + conv_fpn output [k][c64][p]
__device__ float g_Amat[KK*PP*PP];        // sigmoid affinity  [k][i][j]
__device__ float g_dis[KK*PP];            // rsqrt(colsum)
__device__ float g_y1[KK*PP*G16];         // dis_i * (X @ W1)
__device__ float g_x1[KK*PP*G16];         // dis_j * relu(dis_j*agg + b1)
__device__ float g_s_sem[CC], g_t_sem[CC];
__device__ float g_s_fpn[CC], g_t_fpn[CC];
__device__ float g_s_aff[OC64], g_t_aff[OC64];

// ---------------- bn scale/shift precompute -----------------------------------
__global__ void k_bnprep(const float* __restrict__ sg, const float* __restrict__ sb,
                         const float* __restrict__ sm, const float* __restrict__ sv,
                         const float* __restrict__ fg, const float* __restrict__ fb,
                         const float* __restrict__ fm, const float* __restrict__ fv,
                         const float* __restrict__ ag, const float* __restrict__ ab,
                         const float* __restrict__ am, const float* __restrict__ av) {
    int c = threadIdx.x;
    if (c < CC) {
        float s = sg[c] * rsqrtf(sv[c] + 1e-5f);
        g_s_sem[c] = s; g_t_sem[c] = sb[c] - sm[c] * s;
        float f = fg[c] * rsqrtf(fv[c] + 1e-5f);
        g_s_fpn[c] = f; g_t_fpn[c] = fb[c] - fm[c] * f;
    }
    if (c < OC64) {
        float a = ag[c] * rsqrtf(av[c] + 1e-5f);
        g_s_aff[c] = a; g_t_aff[c] = ab[c] - am[c] * a;
    }
}

// ---------------- semantic NCHW -> NHWC transpose ------------------------------
__global__ void __launch_bounds__(256) k_transpose(const float* __restrict__ in) {
    __shared__ float tile[32][33];
    int c0 = blockIdx.x * 32;
    int hw0 = blockIdx.y * 32;
    int b = blockIdx.z;
    const float* ip = in + (size_t)b * CC * HWSZ;
    float* op = g_semt + (size_t)b * HWSZ * CC;
    #pragma unroll
    for (int r = threadIdx.y; r < 32; r += 8)
        tile[r][threadIdx.x] = ip[(c0 + r) * HWSZ + hw0 + threadIdx.x];
    __syncthreads();
    #pragma unroll
    for (int r = threadIdx.y; r < 32; r += 8)
        op[(hw0 + r) * CC + c0 + threadIdx.x] = tile[threadIdx.x][r];
}

// ---------------- bn_relu(roi_feature) -----------------------------------------
__global__ void __launch_bounds__(256) k_actfpn(const float* __restrict__ rf) {
    int i = blockIdx.x * blockDim.x + threadIdx.x;   // float4 index, P=196 divisible by 4
    if (i >= KK * CC * (PP / 4)) return;
    int c = (i / (PP / 4)) % CC;
    float s = g_s_fpn[c], t = g_t_fpn[c];
    float4 v = ((const float4*)rf)[i];
    v.x = fmaxf(v.x * s + t, 0.f); v.y = fmaxf(v.y * s + t, 0.f);
    v.z = fmaxf(v.z * s + t, 0.f); v.w = fmaxf(v.w * s + t, 0.f);
    ((float4*)g_act_fpn)[i] = v;
}

// ---------------- roi_align + bn_relu ------------------------------------------
__global__ void __launch_bounds__(PP) k_roi(const float* __restrict__ boxes) {
    int k = blockIdx.x;
    int p = threadIdx.x;          // 0..195
    int py = p / OSZ, px = p % OSZ;
    const float* bx = boxes + k * 5;
    int bi = (int)bx[0];
    float x1 = bx[1], y1 = bx[2], x2 = bx[3], y2 = bx[4];
    float bw = fmaxf(x2 - x1, 1.f) * (1.f / OSZ);
    float bh = fmaxf(y2 - y1, 1.f) * (1.f / OSZ);

    int yl[2], yh[2]; float fy[2]; bool okY[2];
    int xl[2], xh[2]; float fx[2]; bool okX[2];
    #pragma unroll
    for (int s = 0; s < 2; s++) {
        float t = ((float)(py * 2 + s) + 0.5f) * 0.5f;
        float yc = y1 + bh * t;
        okY[s] = (yc >= -1.f) && (yc <= (float)HH);
        float ycc = fminf(fmaxf(yc, 0.f), (float)(HH - 1));
        int lo = (int)floorf(ycc);
        yl[s] = lo; yh[s] = min(lo + 1, HH - 1); fy[s] = ycc - (float)lo;

        t = ((float)(px * 2 + s) + 0.5f) * 0.5f;
        float xc = x1 + bw * t;
        okX[s] = (xc >= -1.f) && (xc <= (float)WW);
        float xcc = fminf(fmaxf(xc, 0.f), (float)(WW - 1));
        lo = (int)floorf(xcc);
        xl[s] = lo; xh[s] = min(lo + 1, WW - 1); fx[s] = xcc - (float)lo;
    }

    int off[16]; float wt[16];
    #pragma unroll
    for (int sy = 0; sy < 2; sy++) {
        #pragma unroll
        for (int sx = 0; sx < 2; sx++) {
            int q = (sy * 2 + sx) * 4;
            bool ok = okY[sy] && okX[sx];
            float ly = fy[sy], lx = fx[sx];
            float m = ok ? 0.25f : 0.f;
            wt[q + 0] = (1.f - ly) * (1.f - lx) * m;
            wt[q + 1] = (1.f - ly) * lx * m;
            wt[q + 2] = ly * (1.f - lx) * m;
            wt[q + 3] = ly * lx * m;
            int rl = (bi * HH + yl[sy]) * WW, rh = (bi * HH + yh[sy]) * WW;
            off[q + 0] = (rl + xl[sx]) * CC;
            off[q + 1] = (rl + xh[sx]) * CC;
            off[q + 2] = (rh + xl[sx]) * CC;
            off[q + 3] = (rh + xh[sx]) * CC;
        }
    }

    int c0 = blockIdx.y * 64;
    for (int cc = 0; cc < 64; cc += 4) {
        int c = c0 + cc;
        float4 acc = make_float4(0.f, 0.f, 0.f, 0.f);
        #pragma unroll
        for (int t = 0; t < 16; t++) {
            float4 v = *(const float4*)(g_semt + off[t] + c);
            float w = wt[t];
            acc.x += w * v.x; acc.y += w * v.y; acc.z += w * v.z; acc.w += w * v.w;
        }
        float vals[4] = {acc.x, acc.y, acc.z, acc.w};
        #pragma unroll
        for (int q = 0; q < 4; q++) {
            int ch = c + q;
            int idx = (k * CC + ch) * PP + p;
            float v = vals[q];
            g_roi_sem[idx] = v;
            g_act_sem[idx] = fmaxf(v * g_s_sem[ch] + g_t_sem[ch], 0.f);
        }
    }
}

// ---------------- dual 3x3 conv (sem + fpn) + bias, pad=1 ----------------------
__global__ void __launch_bounds__(PP) k_conv(
        const float* __restrict__ wsem, const float* __restrict__ bsem,
        const float* __restrict__ wfpn, const float* __restrict__ bfpn) {
    __shared__ float s_in[2][256];        // 16x16 padded planes
    __shared__ float s_w[2][32][12];      // padded for vector LDS
    int k = blockIdx.x;
    int ocBase = blockIdx.y * 32;
    int p = threadIdx.x;
    int py = p / OSZ, px = p % OSZ;

    float acc[32];
    #pragma unroll
    for (int o = 0; o < 32; o++) acc[o] = 0.f;

    for (int ic = 0; ic < CC; ic++) {
        __syncthreads();
        int base = (k * CC + ic) * PP;
        for (int e = p; e < 256; e += PP) {
            int yy = e >> 4, xx = e & 15;
            int iy = yy - 1, ix = xx - 1;
            bool ok = (iy >= 0) && (iy < OSZ) && (ix >= 0) && (ix < OSZ);
            int src = base + iy * OSZ + ix;
            s_in[0][e] = ok ? g_act_sem[src] : 0.f;
            s_in[1][e] = ok ? g_act_fpn[src] : 0.f;
        }
        for (int j = p; j < 576; j += PP) {
            int cv = j / 288;
            int r = j - cv * 288;
            int oc = r / 9, kk = r - oc * 9;
            const float* wp = cv ? wfpn : wsem;
            s_w[cv][oc][kk] = wp[((ocBase + oc) * CC + ic) * 9 + kk];
        }
        __syncthreads();

        float sv[9], fv[9];
        #pragma unroll
        for (int dy = 0; dy < 3; dy++)
            #pragma unroll
            for (int dx = 0; dx < 3; dx++) {
                int e = (py + dy) * 16 + (px + dx);
                sv[dy * 3 + dx] = s_in[0][e];
                fv[dy * 3 + dx] = s_in[1][e];
            }
        #pragma unroll
        for (int o = 0; o < 32; o++) {
            float t = 0.f;
            #pragma unroll
            for (int kk = 0; kk < 9; kk++) t += s_w[0][o][kk] * sv[kk];
            #pragma unroll
            for (int kk = 0; kk < 9; kk++) t += s_w[1][o][kk] * fv[kk];
            acc[o] += t;
        }
    }
    #pragma unroll
    for (int o = 0; o < 32; o++) {
        int oc = ocBase + o;
        g_a[(k * OC64 + oc) * PP + p] = acc[o] + bsem[oc] + bfpn[oc];
    }
}

// ---------------- bn_relu + 1x1 aff conv + sigmoid + degree --------------------
__global__ void __launch_bounds__(PP) k_aff(const float* __restrict__ waff,
                                            const float* __restrict__ baff) {
    extern __shared__ float s_w[];        // [196][64]
    int k = blockIdx.x;
    int j = threadIdx.x;
    for (int t = j; t < PP * OC64; t += PP) s_w[t] = waff[t];

    float av[OC64];
    #pragma unroll
    for (int c = 0; c < OC64; c++) {
        float v = g_a[(k * OC64 + c) * PP + j];
        av[c] = fmaxf(v * g_s_aff[c] + g_t_aff[c], 0.f);
    }
    __syncthreads();

    float deg = 0.f;
    for (int o = 0; o < PP; o++) {
        float acc = baff[o];
        const float* wr = s_w + o * OC64;
        #pragma unroll
        for (int c = 0; c < OC64; c++) acc += wr[c] * av[c];
        float Av = 1.f / (1.f + __expf(-acc));
        g_Amat[(k * PP + o) * PP + j] = Av;
        deg += Av;
    }
    g_dis[k * PP + j] = rsqrtf(deg);
}

// ---------------- y1 = dis_i * (X @ W1) ----------------------------------------
__global__ void __launch_bounds__(PP) k_y1(const float* __restrict__ rf,
                                           const float* __restrict__ w1) {
    __shared__ float s_w1[CC * G16];
    int k = blockIdx.x;
    int i = threadIdx.x;
    for (int t = i; t < CC * G16; t += PP) s_w1[t] = w1[t];
    __syncthreads();
    float acc[G16];
    #pragma unroll
    for (int g = 0; g < G16; g++) acc[g] = 0.f;
    for (int f = 0; f < CC; f++) {
        float x = rf[(k * CC + f) * PP + i];
        const float* wr = s_w1 + f * G16;
        #pragma unroll
        for (int g = 0; g < G16; g++) acc[g] += x * wr[g];
    }
    float d = g_dis[k * PP + i];
    float* op = g_y1 + (k * PP + i) * G16;
    #pragma unroll
    for (int g = 0; g < G16; g++) op[g] = d * acc[g];
}

// ---------------- x1' = dis_j * relu(dis_j * (A^T y1) + b1) --------------------
__global__ void __launch_bounds__(PP) k_x1(const float* __restrict__ b1) {
    __shared__ float s_y[PP * G16];
    int k = blockIdx.x;
    int j = threadIdx.x;
    for (int t = j; t < PP * G16; t += PP) s_y[t] = g_y1[k * PP * G16 + t];
    __syncthreads();
    float acc[G16];
    #pragma unroll
    for (int g = 0; g < G16; g++) acc[g] = 0.f;
    for (int i = 0; i < PP; i++) {
        float a = g_Amat[(k * PP + i) * PP + j];
        const float* yr = s_y + i * G16;
        #pragma unroll
        for (int g = 0; g < G16; g++) acc[g] += a * yr[g];
    }
    float d = g_dis[k * PP + j];
    float* op = g_x1 + (k * PP + j) * G16;
    #pragma unroll
    for (int g = 0; g < G16; g++)
        op[g] = d * fmaxf(d * acc[g] + b1[g], 0.f);
}

// ---------------- agg2 + final add ---------------------------------------------
#define ZSTRIDE 68
__global__ void __launch_bounds__(PP) k_agg2(const float* __restrict__ w2,
                                             const float* __restrict__ b2,
                                             float* __restrict__ out) {
    extern __shared__ float smdyn[];
    float* s_x = smdyn;                    // [196][16]
    float* s_w2 = smdyn + PP * G16;        // [16][64]
    float* s_Z = s_w2 + G16 * 64;          // [196][68]
    int k = blockIdx.x;
    int c0 = blockIdx.y * 64;
    int j = threadIdx.x;

    for (int t = j; t < PP * G16; t += PP) s_x[t] = g_x1[k * PP * G16 + t];
    for (int t = j; t < G16 * 64; t += PP) {
        int g = t / 64, c = t % 64;
        s_w2[t] = w2[g * CC + c0 + c];
    }
    __syncthreads();

    {   // phase 1: Z[i, c-tile] = x1'[i,:] @ W2[:, c-tile]
        const float* xr = s_x + j * G16;
        float xv[G16];
        #pragma unroll
        for (int g = 0; g < G16; g++) xv[g] = xr[g];
        #pragma unroll 4
        for (int c = 0; c < 64; c++) {
            float t = 0.f;
            #pragma unroll
            for (int g = 0; g < G16; g++) t += xv[g] * s_w2[g * 64 + c];
            s_Z[j * ZSTRIDE + c] = t;
        }
    }
    __syncthreads();

    float acc[64];
    #pragma unroll
    for (int c = 0; c < 64; c++) acc[c] = 0.f;
    for (int i = 0; i < PP; i++) {
        float a = g_Amat[(k * PP + i) * PP + j];
        const float* zr = s_Z + i * ZSTRIDE;
        #pragma unroll
        for (int c = 0; c < 64; c++) acc[c] += a * zr[c];
    }
    float d = g_dis[k * PP + j];
    #pragma unroll
    for (int c = 0; c < 64; c++) {
        int cg = c0 + c;
        int idx = (k * CC + cg) * PP + j;
        out[idx] = g_roi_sem[idx] + b2[cg] + d * acc[c];
    }
}

// ---------------- launch --------------------------------------------------------
extern "C" void kernel_launch(void* const* d_in, const int* in_sizes, int n_in,
                              void* d_out, int out_size) {
    const float* roi_feature = (const float*)d_in[0];
    const float* semantic    = (const float*)d_in[1];
    const float* boxes       = (const float*)d_in[2];
    const float* bn_sem_g = (const float*)d_in[3];
    const float* bn_sem_b = (const float*)d_in[4];
    const float* bn_sem_m = (const float*)d_in[5];
    const float* bn_sem_v = (const float*)d_in[6];
    const float* conv_sem_w = (const float*)d_in[7];
    const float* conv_sem_b = (const float*)d_in[8];
    const float* bn_fpn_g = (const float*)d_in[9];
    const float* bn_fpn_b = (const float*)d_in[10];
    const float* bn_fpn_m = (const float*)d_in[11];
    const float* bn_fpn_v = (const float*)d_in[12];
    const float* conv_fpn_w = (const float*)d_in[13];
    const float* conv_fpn_b = (const float*)d_in[14];
    const float* bn_aff_g = (const float*)d_in[15];
    const float* bn_aff_b = (const float*)d_in[16];
    const float* bn_aff_m = (const float*)d_in[17];
    const float* bn_aff_v = (const float*)d_in[18];
    const float* conv_aff_w = (const float*)d_in[19];
    const float* conv_aff_b = (const float*)d_in[20];
    const float* gcn1_w = (const float*)d_in[21];
    const float* gcn1_b = (const float*)d_in[22];
    const float* gcn2_w = (const float*)d_in[23];
    const float* gcn2_b = (const float*)d_in[24];
    float* out = (float*)d_out;

    static int attr_done = 0;
    if (!attr_done) {
        cudaFuncSetAttribute(k_aff, cudaFuncAttributeMaxDynamicSharedMemorySize,
                             PP * OC64 * 4);
        cudaFuncSetAttribute(k_agg2, cudaFuncAttributeMaxDynamicSharedMemorySize,
                             (PP * G16 + G16 * 64 + PP * ZSTRIDE) * 4);
        attr_done = 1;
    }

    k_bnprep<<<1, 256>>>(bn_sem_g, bn_sem_b, bn_sem_m, bn_sem_v,
                         bn_fpn_g, bn_fpn_b, bn_fpn_m, bn_fpn_v,
                         bn_aff_g, bn_aff_b, bn_aff_m, bn_aff_v);
    k_transpose<<<dim3(CC / 32, HWSZ / 32, BB), dim3(32, 8)>>>(semantic);
    {
        int n4 = KK * CC * (PP / 4);
        k_actfpn<<<(n4 + 255) / 256, 256>>>(roi_feature);
    }
    k_roi<<<dim3(KK, CC / 64), PP>>>(boxes);
    k_conv<<<dim3(KK, 2), PP>>>(conv_sem_w, conv_sem_b, conv_fpn_w, conv_fpn_b);
    k_aff<<<KK, PP, PP * OC64 * 4>>>(conv_aff_w, conv_aff_b);
    k_y1<<<KK, PP>>>(roi_feature, gcn1_w);
    k_x1<<<KK, PP>>>(gcn1_b);
    k_agg2<<<dim3(KK, CC / 64), PP, (PP * G16 + G16 * 64 + PP * ZSTRIDE) * 4>>>(
        gcn2_w, gcn2_b, out);
}

// round 3
// speedup vs baseline: 1.1645x; 1.1645x over previous
#include <cuda_runtime.h>
#include <math.h>

#define KK   256
#define CC   256
#define BB   4
#define HH   112
#define WW   112
#define OSZ  14
#define PP   196      // OSZ*OSZ
#define HWSZ (HH*WW)
#define OC64 64
#define G16  16
#define ICCH 8

typedef unsigned long long u64;

// ---------------- packed fp32x2 helpers (Blackwell FFMA2) ----------------------
__device__ __forceinline__ u64 pack2(float x, float y) {
    u64 r; asm("mov.b64 %0, {%1,%2};" : "=l"(r) : "f"(x), "f"(y)); return r;
}
__device__ __forceinline__ u64 ffma2(u64 a, u64 b, u64 c) {
    u64 d; asm("fma.rn.f32x2 %0, %1, %2, %3;" : "=l"(d) : "l"(a), "l"(b), "l"(c));
    return d;
}
__device__ __forceinline__ float2 unpack2(u64 v) {
    float2 f; asm("mov.b64 {%0,%1}, %2;" : "=f"(f.x), "=f"(f.y) : "l"(v)); return f;
}

// ---------------- scratch (device globals; no allocations allowed) -------------
__device__ float g_semt[BB*HWSZ*CC];      // semantic in NHWC
__device__ float g_roi_sem[KK*CC*PP];     // raw roi-aligned semantic  [k][c][p]
__device__ float g_act_sem[KK*CC*PP];     // bn_relu(roi_sem)
__device__ float g_act_fpn[KK*CC*PP];     // bn_relu(roi_feature)
__device__ float g_a[KK*OC64*PP];         // conv output [k][c64][p]
__device__ float g_Amat[KK*PP*PP];        // sigmoid affinity  [k][i][j]
__device__ float g_dis[KK*PP];            // rsqrt(colsum)
__device__ float g_y1[KK*PP*G16];         // dis_i * (X @ W1)
__device__ float g_x1[KK*PP*G16];         // dis_j * relu(dis_j*agg + b1)
__device__ u64   g_wpack[2*CC*32*9];      // packed conv weights [cv][ic][ocpair32][9]
__device__ float g_s_sem[CC], g_t_sem[CC];
__device__ float g_s_fpn[CC], g_t_fpn[CC];
__device__ float g_s_aff[OC64], g_t_aff[OC64];

// ---------------- bn scale/shift precompute -----------------------------------
__global__ void k_bnprep(const float* __restrict__ sg, const float* __restrict__ sb,
                         const float* __restrict__ sm, const float* __restrict__ sv,
                         const float* __restrict__ fg, const float* __restrict__ fb,
                         const float* __restrict__ fm, const float* __restrict__ fv,
                         const float* __restrict__ ag, const float* __restrict__ ab,
                         const float* __restrict__ am, const float* __restrict__ av) {
    int c = threadIdx.x;
    if (c < CC) {
        float s = sg[c] * rsqrtf(sv[c] + 1e-5f);
        g_s_sem[c] = s; g_t_sem[c] = sb[c] - sm[c] * s;
        float f = fg[c] * rsqrtf(fv[c] + 1e-5f);
        g_s_fpn[c] = f; g_t_fpn[c] = fb[c] - fm[c] * f;
    }
    if (c < OC64) {
        float a = ag[c] * rsqrtf(av[c] + 1e-5f);
        g_s_aff[c] = a; g_t_aff[c] = ab[c] - am[c] * a;
    }
}

// ---------------- weight pre-pack: oc-pairs for FFMA2 --------------------------
// g_wpack[((cv*CC + ic)*32 + prg)*9 + kk] = {w[2prg][ic][kk], w[2prg+1][ic][kk]}
__global__ void __launch_bounds__(256) k_wpack(const float* __restrict__ wsem,
                                               const float* __restrict__ wfpn) {
    int i = blockIdx.x * 256 + threadIdx.x;
    if (i >= 2 * CC * 32 * 9) return;
    int kk = i % 9; int r = i / 9;
    int prg = r % 32; r /= 32;
    int icg = r % CC; int cv = r / CC;
    const float* w = cv ? wfpn : wsem;
    float x = w[((2 * prg) * CC + icg) * 9 + kk];
    float y = w[((2 * prg + 1) * CC + icg) * 9 + kk];
    g_wpack[i] = pack2(x, y);
}

// ---------------- semantic NCHW -> NHWC transpose ------------------------------
__global__ void __launch_bounds__(256) k_transpose(const float* __restrict__ in) {
    __shared__ float tile[32][33];
    int c0 = blockIdx.x * 32;
    int hw0 = blockIdx.y * 32;
    int b = blockIdx.z;
    const float* ip = in + (size_t)b * CC * HWSZ;
    float* op = g_semt + (size_t)b * HWSZ * CC;
    #pragma unroll
    for (int r = threadIdx.y; r < 32; r += 8)
        tile[r][threadIdx.x] = ip[(c0 + r) * HWSZ + hw0 + threadIdx.x];
    __syncthreads();
    #pragma unroll
    for (int r = threadIdx.y; r < 32; r += 8)
        op[(hw0 + r) * CC + c0 + threadIdx.x] = tile[threadIdx.x][r];
}

// ---------------- bn_relu(roi_feature) -----------------------------------------
__global__ void __launch_bounds__(256) k_actfpn(const float* __restrict__ rf) {
    int i = blockIdx.x * blockDim.x + threadIdx.x;
    if (i >= KK * CC * (PP / 4)) return;
    int c = (i / (PP / 4)) % CC;
    float s = g_s_fpn[c], t = g_t_fpn[c];
    float4 v = ((const float4*)rf)[i];
    v.x = fmaxf(v.x * s + t, 0.f); v.y = fmaxf(v.y * s + t, 0.f);
    v.z = fmaxf(v.z * s + t, 0.f); v.w = fmaxf(v.w * s + t, 0.f);
    ((float4*)g_act_fpn)[i] = v;
}

// ---------------- roi_align + bn_relu (channel-major coalesced gathers) --------
// block = 256 threads (64 c-lanes x 4 p-lanes), grid = KK
// dyn smem: s_out[256][29] | s_wt[196][16] | s_off[196][16]
#define ROI_SMEM (256*29*4 + PP*16*4 + PP*16*4)
__global__ void __launch_bounds__(256) k_roi(const float* __restrict__ boxes) {
    extern __shared__ float smdyn[];
    float* s_out = smdyn;                       // [256][29]
    float* s_wt  = smdyn + 256 * 29;            // [196][16]
    int*   s_off = (int*)(smdyn + 256 * 29 + PP * 16);  // [196][16]

    int k = blockIdx.x;
    int t = threadIdx.x;
    int x = t & 63;          // c-lane
    int y = t >> 6;          // p-lane

    // ---- prologue: per-p bilinear weights/offsets ----
    if (t < PP) {
        int p = t;
        int py = p / OSZ, px = p % OSZ;
        const float* bx = boxes + k * 5;
        int bi = (int)bx[0];
        float x1 = bx[1], y1 = bx[2], x2 = bx[3], y2 = bx[4];
        float bw = fmaxf(x2 - x1, 1.f) * (1.f / OSZ);
        float bh = fmaxf(y2 - y1, 1.f) * (1.f / OSZ);

        int yl[2], yh[2]; float fy[2]; bool okY[2];
        int xl[2], xh[2]; float fx[2]; bool okX[2];
        #pragma unroll
        for (int s = 0; s < 2; s++) {
            float tt = ((float)(py * 2 + s) + 0.5f) * 0.5f;
            float yc = y1 + bh * tt;
            okY[s] = (yc >= -1.f) && (yc <= (float)HH);
            float ycc = fminf(fmaxf(yc, 0.f), (float)(HH - 1));
            int lo = (int)floorf(ycc);
            yl[s] = lo; yh[s] = min(lo + 1, HH - 1); fy[s] = ycc - (float)lo;

            tt = ((float)(px * 2 + s) + 0.5f) * 0.5f;
            float xc = x1 + bw * tt;
            okX[s] = (xc >= -1.f) && (xc <= (float)WW);
            float xcc = fminf(fmaxf(xc, 0.f), (float)(WW - 1));
            lo = (int)floorf(xcc);
            xl[s] = lo; xh[s] = min(lo + 1, WW - 1); fx[s] = xcc - (float)lo;
        }
        #pragma unroll
        for (int sy = 0; sy < 2; sy++) {
            #pragma unroll
            for (int sx = 0; sx < 2; sx++) {
                int q = (sy * 2 + sx) * 4;
                bool ok = okY[sy] && okX[sx];
                float ly = fy[sy], lx = fx[sx];
                float m = ok ? 0.25f : 0.f;
                s_wt[p * 16 + q + 0] = (1.f - ly) * (1.f - lx) * m;
                s_wt[p * 16 + q + 1] = (1.f - ly) * lx * m;
                s_wt[p * 16 + q + 2] = ly * (1.f - lx) * m;
                s_wt[p * 16 + q + 3] = ly * lx * m;
                int rl = (bi * HH + yl[sy]) * WW, rh = (bi * HH + yh[sy]) * WW;
                s_off[p * 16 + q + 0] = (rl + xl[sx]) * CC;
                s_off[p * 16 + q + 1] = (rl + xh[sx]) * CC;
                s_off[p * 16 + q + 2] = (rh + xl[sx]) * CC;
                s_off[p * 16 + q + 3] = (rh + xh[sx]) * CC;
            }
        }
    }
    __syncthreads();

    int wid = t >> 5, lane = t & 31;
    for (int tile = 0; tile < 7; tile++) {          // 7 tiles of 28 p
        #pragma unroll
        for (int pass = 0; pass < 7; pass++) {      // 4 p per pass
            int pl = pass * 4 + y;                  // 0..27
            int p = tile * 28 + pl;
            const float* wr = s_wt + p * 16;
            const int*   orow = s_off + p * 16;
            float4 acc = make_float4(0.f, 0.f, 0.f, 0.f);
            int c = x * 4;
            #pragma unroll
            for (int q = 0; q < 16; q++) {
                float4 v = *(const float4*)(g_semt + orow[q] + c);
                float w = wr[q];
                acc.x += w * v.x; acc.y += w * v.y;
                acc.z += w * v.z; acc.w += w * v.w;
            }
            s_out[(c + 0) * 29 + pl] = acc.x;
            s_out[(c + 1) * 29 + pl] = acc.y;
            s_out[(c + 2) * 29 + pl] = acc.z;
            s_out[(c + 3) * 29 + pl] = acc.w;
        }
        __syncthreads();
        // coalesced store along p
        if (lane < 28) {
            int pg = tile * 28 + lane;
            #pragma unroll
            for (int rr = 0; rr < 32; rr++) {
                int r = wid * 32 + rr;
                float v = s_out[r * 29 + lane];
                int idx = (k * CC + r) * PP + pg;
                g_roi_sem[idx] = v;
                g_act_sem[idx] = fmaxf(v * g_s_sem[r] + g_t_sem[r], 0.f);
            }
        }
        __syncthreads();
    }
}

// ---------------- dual 3x3 conv, FFMA2 packed over oc-pairs --------------------
__global__ void __launch_bounds__(PP) k_conv(const float* __restrict__ bsem,
                                             const float* __restrict__ bfpn) {
    __shared__ float s_in[ICCH][2][256];        // 16x16 padded planes
    __shared__ u64 s_wp[2][ICCH][16][10];       // pair weights, row padded to 10
    int k = blockIdx.x;
    int ocblk = blockIdx.y;                     // 0..1  (32 oc each)
    int p = threadIdx.x;
    int py = p / OSZ, px = p % OSZ;

    u64 acc2[16];
    #pragma unroll
    for (int o = 0; o < 16; o++) acc2[o] = 0ull;

    for (int ic0 = 0; ic0 < CC; ic0 += ICCH) {
        __syncthreads();
        // stage inputs (both convs, 8 ics)
        for (int e = p; e < ICCH * 2 * 256; e += PP) {
            int icl = e >> 9; int cv = (e >> 8) & 1; int pos = e & 255;
            int yy = pos >> 4, xx = pos & 15;
            int iy = yy - 1, ix = xx - 1;
            bool ok = (iy >= 0) && (iy < OSZ) && (ix >= 0) && (ix < OSZ);
            const float* src = cv ? g_act_fpn : g_act_sem;
            s_in[icl][cv][pos] = ok ? src[(k * CC + ic0 + icl) * PP + iy * OSZ + ix] : 0.f;
        }
        // stage packed weights
        for (int j = p; j < 2 * ICCH * 16 * 9; j += PP) {
            int cv = j / (ICCH * 16 * 9); int r = j - cv * (ICCH * 16 * 9);
            int icl = r / 144; int r2 = r - icl * 144;
            int pr = r2 / 9; int kk = r2 - pr * 9;
            s_wp[cv][icl][pr][kk] =
                g_wpack[((cv * CC + ic0 + icl) * 32 + ocblk * 16 + pr) * 9 + kk];
        }
        __syncthreads();

        #pragma unroll
        for (int icl = 0; icl < ICCH; icl++) {
            #pragma unroll
            for (int cv = 0; cv < 2; cv++) {
                u64 v2[9];
                #pragma unroll
                for (int dy = 0; dy < 3; dy++)
                    #pragma unroll
                    for (int dx = 0; dx < 3; dx++) {
                        float v = s_in[icl][cv][(py + dy) * 16 + (px + dx)];
                        v2[dy * 3 + dx] = pack2(v, v);
                    }
                #pragma unroll
                for (int pr = 0; pr < 16; pr++) {
                    const u64* w = s_wp[cv][icl][pr];
                    u64 a = acc2[pr];
                    #pragma unroll
                    for (int kk = 0; kk < 9; kk++) a = ffma2(w[kk], v2[kk], a);
                    acc2[pr] = a;
                }
            }
        }
    }
    #pragma unroll
    for (int pr = 0; pr < 16; pr++) {
        float2 v = unpack2(acc2[pr]);
        int oc0 = ocblk * 32 + 2 * pr;
        g_a[(k * OC64 + oc0) * PP + p]     = v.x + bsem[oc0] + bfpn[oc0];
        g_a[(k * OC64 + oc0 + 1) * PP + p] = v.y + bsem[oc0 + 1] + bfpn[oc0 + 1];
    }
}

// ---------------- bn_relu + 1x1 aff conv + sigmoid + degree --------------------
__global__ void __launch_bounds__(PP) k_aff(const float* __restrict__ waff,
                                            const float* __restrict__ baff) {
    extern __shared__ float s_w[];        // [196][64]
    int k = blockIdx.x;
    int j = threadIdx.x;
    for (int t = j; t < PP * OC64; t += PP) s_w[t] = waff[t];

    u64 av2[32];
    #pragma unroll
    for (int c = 0; c < 32; c++) {
        float v0 = g_a[(k * OC64 + 2 * c) * PP + j];
        float v1 = g_a[(k * OC64 + 2 * c + 1) * PP + j];
        v0 = fmaxf(v0 * g_s_aff[2 * c] + g_t_aff[2 * c], 0.f);
        v1 = fmaxf(v1 * g_s_aff[2 * c + 1] + g_t_aff[2 * c + 1], 0.f);
        av2[c] = pack2(v0, v1);
    }
    __syncthreads();

    float deg = 0.f;
    for (int o = 0; o < PP; o++) {
        const u64* wr = (const u64*)(s_w + o * OC64);
        u64 acc = 0ull;
        #pragma unroll
        for (int c = 0; c < 32; c++) acc = ffma2(wr[c], av2[c], acc);
        float2 s = unpack2(acc);
        float f = baff[o] + s.x + s.y;
        float Av = 1.f / (1.f + __expf(-f));
        g_Amat[(k * PP + o) * PP + j] = Av;
        deg += Av;
    }
    g_dis[k * PP + j] = rsqrtf(deg);
}

// ---------------- y1 = dis_i * (X @ W1) ----------------------------------------
__global__ void __launch_bounds__(PP) k_y1(const float* __restrict__ rf,
                                           const float* __restrict__ w1) {
    __shared__ float s_w1[CC * G16];
    int k = blockIdx.x;
    int i = threadIdx.x;
    for (int t = i; t < CC * G16; t += PP) s_w1[t] = w1[t];
    __syncthreads();
    u64 acc[8];
    #pragma unroll
    for (int g = 0; g < 8; g++) acc[g] = 0ull;
    for (int f = 0; f < CC; f++) {
        float xv = rf[(k * CC + f) * PP + i];
        u64 x2 = pack2(xv, xv);
        const u64* wr = (const u64*)(s_w1 + f * G16);
        #pragma unroll
        for (int g = 0; g < 8; g++) acc[g] = ffma2(x2, wr[g], acc[g]);
    }
    float d = g_dis[k * PP + i];
    float* op = g_y1 + (k * PP + i) * G16;
    #pragma unroll
    for (int g = 0; g < 8; g++) {
        float2 v = unpack2(acc[g]);
        op[2 * g] = d * v.x; op[2 * g + 1] = d * v.y;
    }
}

// ---------------- x1' = dis_j * relu(dis_j * (A^T y1) + b1) --------------------
__global__ void __launch_bounds__(PP) k_x1(const float* __restrict__ b1) {
    __shared__ float s_y[PP * G16];
    int k = blockIdx.x;
    int j = threadIdx.x;
    for (int t = j; t < PP * G16; t += PP) s_y[t] = g_y1[k * PP * G16 + t];
    __syncthreads();
    u64 acc[8];
    #pragma unroll
    for (int g = 0; g < 8; g++) acc[g] = 0ull;
    for (int i = 0; i < PP; i++) {
        float a = g_Amat[(k * PP + i) * PP + j];
        u64 a2 = pack2(a, a);
        const u64* yr = (const u64*)(s_y + i * G16);
        #pragma unroll
        for (int g = 0; g < 8; g++) acc[g] = ffma2(a2, yr[g], acc[g]);
    }
    float d = g_dis[k * PP + j];
    float* op = g_x1 + (k * PP + j) * G16;
    #pragma unroll
    for (int g = 0; g < 8; g++) {
        float2 v = unpack2(acc[g]);
        op[2 * g]     = d * fmaxf(d * v.x + b1[2 * g], 0.f);
        op[2 * g + 1] = d * fmaxf(d * v.y + b1[2 * g + 1], 0.f);
    }
}

// ---------------- agg2 + final add ---------------------------------------------
#define ZSTRIDE 68
__global__ void __launch_bounds__(PP) k_agg2(const float* __restrict__ w2,
                                             const float* __restrict__ b2,
                                             float* __restrict__ out) {
    extern __shared__ float smdyn[];
    float* s_x = smdyn;                    // [196][16]
    float* s_w2 = smdyn + PP * G16;        // [16][64]
    float* s_Z = s_w2 + G16 * 64;          // [196][68]
    int k = blockIdx.x;
    int c0 = blockIdx.y * 64;
    int j = threadIdx.x;

    for (int t = j; t < PP * G16; t += PP) s_x[t] = g_x1[k * PP * G16 + t];
    for (int t = j; t < G16 * 64; t += PP) {
        int g = t / 64, c = t % 64;
        s_w2[t] = w2[g * CC + c0 + c];
    }
    __syncthreads();

    {   // phase 1: Z[i, c-tile] = x1'[i,:] @ W2[:, c-tile]
        const float* xr = s_x + j * G16;
        float xv[G16];
        #pragma unroll
        for (int g = 0; g < G16; g++) xv[g] = xr[g];
        #pragma unroll 4
        for (int c = 0; c < 64; c++) {
            float t = 0.f;
            #pragma unroll
            for (int g = 0; g < G16; g++) t += xv[g] * s_w2[g * 64 + c];
            s_Z[j * ZSTRIDE + c] = t;
        }
    }
    __syncthreads();

    u64 acc[32];
    #pragma unroll
    for (int c = 0; c < 32; c++) acc[c] = 0ull;
    for (int i = 0; i < PP; i++) {
        float a = g_Amat[(k * PP + i) * PP + j];
        u64 a2 = pack2(a, a);
        const u64* zr = (const u64*)(s_Z + i * ZSTRIDE);
        #pragma unroll
        for (int c = 0; c < 32; c++) acc[c] = ffma2(a2, zr[c], acc[c]);
    }
    float d = g_dis[k * PP + j];
    #pragma unroll
    for (int c = 0; c < 32; c++) {
        float2 v = unpack2(acc[c]);
        int cg0 = c0 + 2 * c;
        int idx0 = (k * CC + cg0) * PP + j;
        out[idx0]      = g_roi_sem[idx0] + b2[cg0] + d * v.x;
        out[idx0 + PP] = g_roi_sem[idx0 + PP] + b2[cg0 + 1] + d * v.y;
    }
}

// ---------------- launch --------------------------------------------------------
extern "C" void kernel_launch(void* const* d_in, const int* in_sizes, int n_in,
                              void* d_out, int out_size) {
    const float* roi_feature = (const float*)d_in[0];
    const float* semantic    = (const float*)d_in[1];
    const float* boxes       = (const float*)d_in[2];
    const float* bn_sem_g = (const float*)d_in[3];
    const float* bn_sem_b = (const float*)d_in[4];
    const float* bn_sem_m = (const float*)d_in[5];
    const float* bn_sem_v = (const float*)d_in[6];
    const float* conv_sem_w = (const float*)d_in[7];
    const float* conv_sem_b = (const float*)d_in[8];
    const float* bn_fpn_g = (const float*)d_in[9];
    const float* bn_fpn_b = (const float*)d_in[10];
    const float* bn_fpn_m = (const float*)d_in[11];
    const float* bn_fpn_v = (const float*)d_in[12];
    const float* conv_fpn_w = (const float*)d_in[13];
    const float* conv_fpn_b = (const float*)d_in[14];
    const float* bn_aff_g = (const float*)d_in[15];
    const float* bn_aff_b = (const float*)d_in[16];
    const float* bn_aff_m = (const float*)d_in[17];
    const float* bn_aff_v = (const float*)d_in[18];
    const float* conv_aff_w = (const float*)d_in[19];
    const float* conv_aff_b = (const float*)d_in[20];
    const float* gcn1_w = (const float*)d_in[21];
    const float* gcn1_b = (const float*)d_in[22];
    const float* gcn2_w = (const float*)d_in[23];
    const float* gcn2_b = (const float*)d_in[24];
    float* out = (float*)d_out;

    static int attr_done = 0;
    if (!attr_done) {
        cudaFuncSetAttribute(k_roi, cudaFuncAttributeMaxDynamicSharedMemorySize,
                             ROI_SMEM);
        cudaFuncSetAttribute(k_aff, cudaFuncAttributeMaxDynamicSharedMemorySize,
                             PP * OC64 * 4);
        cudaFuncSetAttribute(k_agg2, cudaFuncAttributeMaxDynamicSharedMemorySize,
                             (PP * G16 + G16 * 64 + PP * ZSTRIDE) * 4);
        attr_done = 1;
    }

    k_bnprep<<<1, 256>>>(bn_sem_g, bn_sem_b, bn_sem_m, bn_sem_v,
                         bn_fpn_g, bn_fpn_b, bn_fpn_m, bn_fpn_v,
                         bn_aff_g, bn_aff_b, bn_aff_m, bn_aff_v);
    k_wpack<<<(2 * CC * 32 * 9 + 255) / 256, 256>>>(conv_sem_w, conv_fpn_w);
    k_transpose<<<dim3(CC / 32, HWSZ / 32, BB), dim3(32, 8)>>>(semantic);
    {
        int n4 = KK * CC * (PP / 4);
        k_actfpn<<<(n4 + 255) / 256, 256>>>(roi_feature);
    }
    k_roi<<<KK, 256, ROI_SMEM>>>(boxes);
    k_conv<<<dim3(KK, 2), PP>>>(conv_sem_b, conv_fpn_b);
    k_aff<<<KK, PP, PP * OC64 * 4>>>(conv_aff_w, conv_aff_b);
    k_y1<<<KK, PP>>>(roi_feature, gcn1_w);
    k_x1<<<KK, PP>>>(gcn1_b);
    k_agg2<<<dim3(KK, CC / 64), PP, (PP * G16 + G16 * 64 + PP * ZSTRIDE) * 4>>>(
        gcn2_w, gcn2_b, out);
}

// round 5
// speedup vs baseline: 1.1680x; 1.0030x over previous
#include <cuda_runtime.h>
#include <math.h>

#define KK   256
#define CC   256
#define BB   4
#define HH   112
#define WW   112
#define OSZ  14
#define PP   196      // OSZ*OSZ
#define HWSZ (HH*WW)
#define OC64 64
#define G16  16
#define ICCH 8

typedef unsigned long long u64;

// ---------------- packed fp32x2 helpers (Blackwell FFMA2) ----------------------
__device__ __forceinline__ u64 pack2(float x, float y) {
    u64 r; asm("mov.b64 %0, {%1,%2};" : "=l"(r) : "f"(x), "f"(y)); return r;
}
__device__ __forceinline__ u64 ffma2(u64 a, u64 b, u64 c) {
    u64 d; asm("fma.rn.f32x2 %0, %1, %2, %3;" : "=l"(d) : "l"(a), "l"(b), "l"(c));
    return d;
}
__device__ __forceinline__ float2 unpack2(u64 v) {
    float2 f; asm("mov.b64 {%0,%1}, %2;" : "=f"(f.x), "=f"(f.y) : "l"(v)); return f;
}

// ---------------- scratch (device globals; no allocations allowed) -------------
__device__ float g_semt[BB*HWSZ*CC];      // semantic in NHWC
__device__ float g_roi_sem[KK*CC*PP];     // raw roi-aligned semantic  [k][c][p]
__device__ float g_act_sem[KK*CC*PP];     // bn_relu(roi_sem)
__device__ float g_act_fpn[KK*CC*PP];     // bn_relu(roi_feature)
__device__ float g_a[KK*OC64*PP];         // conv output [k][c64][p]
__device__ float g_Amat[KK*PP*PP];        // sigmoid affinity  [k][i][j]
__device__ float g_dis[KK*PP];            // rsqrt(colsum)
__device__ float g_y1[KK*PP*G16];         // dis_i * (X @ W1)
__device__ float g_x1[KK*PP*G16];         // dis_j * relu(dis_j*agg + b1)
__device__ u64   g_wpack[2*CC*32*9];      // packed conv weights [cv][ic][ocpair32][9]
__device__ float g_s_sem[CC], g_t_sem[CC];
__device__ float g_s_fpn[CC], g_t_fpn[CC];
__device__ float g_s_aff[OC64], g_t_aff[OC64];

// ---------------- bn scale/shift precompute -----------------------------------
__global__ void k_bnprep(const float* __restrict__ sg, const float* __restrict__ sb,
                         const float* __restrict__ sm, const float* __restrict__ sv,
                         const float* __restrict__ fg, const float* __restrict__ fb,
                         const float* __restrict__ fm, const float* __restrict__ fv,
                         const float* __restrict__ ag, const float* __restrict__ ab,
                         const float* __restrict__ am, const float* __restrict__ av) {
    int c = threadIdx.x;
    if (c < CC) {
        float s = sg[c] * rsqrtf(sv[c] + 1e-5f);
        g_s_sem[c] = s; g_t_sem[c] = sb[c] - sm[c] * s;
        float f = fg[c] * rsqrtf(fv[c] + 1e-5f);
        g_s_fpn[c] = f; g_t_fpn[c] = fb[c] - fm[c] * f;
    }
    if (c < OC64) {
        float a = ag[c] * rsqrtf(av[c] + 1e-5f);
        g_s_aff[c] = a; g_t_aff[c] = ab[c] - am[c] * a;
    }
}

// ---------------- weight pre-pack: oc-pairs for FFMA2 --------------------------
// g_wpack[((cv*CC + ic)*32 + prg)*9 + kk] = {w[2prg][ic][kk], w[2prg+1][ic][kk]}
__global__ void __launch_bounds__(256) k_wpack(const float* __restrict__ wsem,
                                               const float* __restrict__ wfpn) {
    int i = blockIdx.x * 256 + threadIdx.x;
    if (i >= 2 * CC * 32 * 9) return;
    int kk = i % 9; int r = i / 9;
    int prg = r % 32; r /= 32;
    int icg = r % CC; int cv = r / CC;
    const float* w = cv ? wfpn : wsem;
    float x = w[((2 * prg) * CC + icg) * 9 + kk];
    float y = w[((2 * prg + 1) * CC + icg) * 9 + kk];
    g_wpack[i] = pack2(x, y);
}

// ---------------- semantic NCHW -> NHWC transpose ------------------------------
__global__ void __launch_bounds__(256) k_transpose(const float* __restrict__ in) {
    __shared__ float tile[32][33];
    int c0 = blockIdx.x * 32;
    int hw0 = blockIdx.y * 32;
    int b = blockIdx.z;
    const float* ip = in + (size_t)b * CC * HWSZ;
    float* op = g_semt + (size_t)b * HWSZ * CC;
    #pragma unroll
    for (int r = threadIdx.y; r < 32; r += 8)
        tile[r][threadIdx.x] = ip[(c0 + r) * HWSZ + hw0 + threadIdx.x];
    __syncthreads();
    #pragma unroll
    for (int r = threadIdx.y; r < 32; r += 8)
        op[(hw0 + r) * CC + c0 + threadIdx.x] = tile[threadIdx.x][r];
}

// ---------------- bn_relu(roi_feature) -----------------------------------------
__global__ void __launch_bounds__(256) k_actfpn(const float* __restrict__ rf) {
    int i = blockIdx.x * blockDim.x + threadIdx.x;
    if (i >= KK * CC * (PP / 4)) return;
    int c = (i / (PP / 4)) % CC;
    float s = g_s_fpn[c], t = g_t_fpn[c];
    float4 v = ((const float4*)rf)[i];
    v.x = fmaxf(v.x * s + t, 0.f); v.y = fmaxf(v.y * s + t, 0.f);
    v.z = fmaxf(v.z * s + t, 0.f); v.w = fmaxf(v.w * s + t, 0.f);
    ((float4*)g_act_fpn)[i] = v;
}

// ---------------- roi_align + bn_relu (channel-major coalesced gathers) --------
// block = 256 threads (64 c-lanes x 4 p-lanes), grid = KK
// dyn smem: s_out[256][29] | s_wt[196][16] | s_off[196][16]
#define ROI_SMEM (256*29*4 + PP*16*4 + PP*16*4)
__global__ void __launch_bounds__(256) k_roi(const float* __restrict__ boxes) {
    extern __shared__ float smdyn[];
    float* s_out = smdyn;                       // [256][29]
    float* s_wt  = smdyn + 256 * 29;            // [196][16]
    int*   s_off = (int*)(smdyn + 256 * 29 + PP * 16);  // [196][16]

    int k = blockIdx.x;
    int t = threadIdx.x;
    int x = t & 63;          // c-lane
    int y = t >> 6;          // p-lane

    // ---- prologue: per-p bilinear weights/offsets ----
    if (t < PP) {
        int p = t;
        int py = p / OSZ, px = p % OSZ;
        const float* bx = boxes + k * 5;
        int bi = (int)bx[0];
        float x1 = bx[1], y1 = bx[2], x2 = bx[3], y2 = bx[4];
        float bw = fmaxf(x2 - x1, 1.f) * (1.f / OSZ);
        float bh = fmaxf(y2 - y1, 1.f) * (1.f / OSZ);

        int yl[2], yh[2]; float fy[2]; bool okY[2];
        int xl[2], xh[2]; float fx[2]; bool okX[2];
        #pragma unroll
        for (int s = 0; s < 2; s++) {
            float tt = ((float)(py * 2 + s) + 0.5f) * 0.5f;
            float yc = y1 + bh * tt;
            okY[s] = (yc >= -1.f) && (yc <= (float)HH);
            float ycc = fminf(fmaxf(yc, 0.f), (float)(HH - 1));
            int lo = (int)floorf(ycc);
            yl[s] = lo; yh[s] = min(lo + 1, HH - 1); fy[s] = ycc - (float)lo;

            tt = ((float)(px * 2 + s) + 0.5f) * 0.5f;
            float xc = x1 + bw * tt;
            okX[s] = (xc >= -1.f) && (xc <= (float)WW);
            float xcc = fminf(fmaxf(xc, 0.f), (float)(WW - 1));
            lo = (int)floorf(xcc);
            xl[s] = lo; xh[s] = min(lo + 1, WW - 1); fx[s] = xcc - (float)lo;
        }
        #pragma unroll
        for (int sy = 0; sy < 2; sy++) {
            #pragma unroll
            for (int sx = 0; sx < 2; sx++) {
                int q = (sy * 2 + sx) * 4;
                bool ok = okY[sy] && okX[sx];
                float ly = fy[sy], lx = fx[sx];
                float m = ok ? 0.25f : 0.f;
                s_wt[p * 16 + q + 0] = (1.f - ly) * (1.f - lx) * m;
                s_wt[p * 16 + q + 1] = (1.f - ly) * lx * m;
                s_wt[p * 16 + q + 2] = ly * (1.f - lx) * m;
                s_wt[p * 16 + q + 3] = ly * lx * m;
                int rl = (bi * HH + yl[sy]) * WW, rh = (bi * HH + yh[sy]) * WW;
                s_off[p * 16 + q + 0] = (rl + xl[sx]) * CC;
                s_off[p * 16 + q + 1] = (rl + xh[sx]) * CC;
                s_off[p * 16 + q + 2] = (rh + xl[sx]) * CC;
                s_off[p * 16 + q + 3] = (rh + xh[sx]) * CC;
            }
        }
    }
    __syncthreads();

    int wid = t >> 5, lane = t & 31;
    for (int tile = 0; tile < 7; tile++) {          // 7 tiles of 28 p
        #pragma unroll
        for (int pass = 0; pass < 7; pass++) {      // 4 p per pass
            int pl = pass * 4 + y;                  // 0..27
            int p = tile * 28 + pl;
            const float* wr = s_wt + p * 16;
            const int*   orow = s_off + p * 16;
            float4 acc = make_float4(0.f, 0.f, 0.f, 0.f);
            int c = x * 4;
            #pragma unroll
            for (int q = 0; q < 16; q++) {
                float4 v = *(const float4*)(g_semt + orow[q] + c);
                float w = wr[q];
                acc.x += w * v.x; acc.y += w * v.y;
                acc.z += w * v.z; acc.w += w * v.w;
            }
            s_out[(c + 0) * 29 + pl] = acc.x;
            s_out[(c + 1) * 29 + pl] = acc.y;
            s_out[(c + 2) * 29 + pl] = acc.z;
            s_out[(c + 3) * 29 + pl] = acc.w;
        }
        __syncthreads();
        // coalesced store along p
        if (lane < 28) {
            int pg = tile * 28 + lane;
            #pragma unroll
            for (int rr = 0; rr < 32; rr++) {
                int r = wid * 32 + rr;
                float v = s_out[r * 29 + lane];
                int idx = (k * CC + r) * PP + pg;
                g_roi_sem[idx] = v;
                g_act_sem[idx] = fmaxf(v * g_s_sem[r] + g_t_sem[r], 0.f);
            }
        }
        __syncthreads();
    }
}

// ---------------- dual 3x3 conv, FFMA2 packed over oc-pairs --------------------
__global__ void __launch_bounds__(PP) k_conv(const float* __restrict__ bsem,
                                             const float* __restrict__ bfpn) {
    __shared__ float s_in[ICCH][2][256];        // 16x16 padded planes
    __shared__ u64 s_wp[2][ICCH][16][10];       // pair weights, row padded to 10
    int k = blockIdx.x;
    int ocblk = blockIdx.y;                     // 0..1  (32 oc each)
    int p = threadIdx.x;
    int py = p / OSZ, px = p % OSZ;

    u64 acc2[16];
    #pragma unroll
    for (int o = 0; o < 16; o++) acc2[o] = 0ull;

    for (int ic0 = 0; ic0 < CC; ic0 += ICCH) {
        __syncthreads();
        // stage inputs (both convs, 8 ics)
        for (int e = p; e < ICCH * 2 * 256; e += PP) {
            int icl = e >> 9; int cv = (e >> 8) & 1; int pos = e & 255;
            int yy = pos >> 4, xx = pos & 15;
            int iy = yy - 1, ix = xx - 1;
            bool ok = (iy >= 0) && (iy < OSZ) && (ix >= 0) && (ix < OSZ);
            const float* src = cv ? g_act_fpn : g_act_sem;
            s_in[icl][cv][pos] = ok ? src[(k * CC + ic0 + icl) * PP + iy * OSZ + ix] : 0.f;
        }
        // stage packed weights
        for (int j = p; j < 2 * ICCH * 16 * 9; j += PP) {
            int cv = j / (ICCH * 16 * 9); int r = j - cv * (ICCH * 16 * 9);
            int icl = r / 144; int r2 = r - icl * 144;
            int pr = r2 / 9; int kk = r2 - pr * 9;
            s_wp[cv][icl][pr][kk] =
                g_wpack[((cv * CC + ic0 + icl) * 32 + ocblk * 16 + pr) * 9 + kk];
        }
        __syncthreads();

        #pragma unroll
        for (int icl = 0; icl < ICCH; icl++) {
            #pragma unroll
            for (int cv = 0; cv < 2; cv++) {
                u64 v2[9];
                #pragma unroll
                for (int dy = 0; dy < 3; dy++)
                    #pragma unroll
                    for (int dx = 0; dx < 3; dx++) {
                        float v = s_in[icl][cv][(py + dy) * 16 + (px + dx)];
                        v2[dy * 3 + dx] = pack2(v, v);
                    }
                #pragma unroll
                for (int pr = 0; pr < 16; pr++) {
                    const u64* w = s_wp[cv][icl][pr];
                    u64 a = acc2[pr];
                    #pragma unroll
                    for (int kk = 0; kk < 9; kk++) a = ffma2(w[kk], v2[kk], a);
                    acc2[pr] = a;
                }
            }
        }
    }
    #pragma unroll
    for (int pr = 0; pr < 16; pr++) {
        float2 v = unpack2(acc2[pr]);
        int oc0 = ocblk * 32 + 2 * pr;
        g_a[(k * OC64 + oc0) * PP + p]     = v.x + bsem[oc0] + bfpn[oc0];
        g_a[(k * OC64 + oc0 + 1) * PP + p] = v.y + bsem[oc0 + 1] + bfpn[oc0 + 1];
    }
}

// ---------------- bn_relu + 1x1 aff conv + sigmoid + degree --------------------
__global__ void __launch_bounds__(PP) k_aff(const float* __restrict__ waff,
                                            const float* __restrict__ baff) {
    extern __shared__ float s_w[];        // [196][64]
    int k = blockIdx.x;
    int j = threadIdx.x;
    for (int t = j; t < PP * OC64; t += PP) s_w[t] = waff[t];

    u64 av2[32];
    #pragma unroll
    for (int c = 0; c < 32; c++) {
        float v0 = g_a[(k * OC64 + 2 * c) * PP + j];
        float v1 = g_a[(k * OC64 + 2 * c + 1) * PP + j];
        v0 = fmaxf(v0 * g_s_aff[2 * c] + g_t_aff[2 * c], 0.f);
        v1 = fmaxf(v1 * g_s_aff[2 * c + 1] + g_t_aff[2 * c + 1], 0.f);
        av2[c] = pack2(v0, v1);
    }
    __syncthreads();

    float deg = 0.f;
    for (int o = 0; o < PP; o++) {
        const u64* wr = (const u64*)(s_w + o * OC64);
        u64 acc = 0ull;
        #pragma unroll
        for (int c = 0; c < 32; c++) acc = ffma2(wr[c], av2[c], acc);
        float2 s = unpack2(acc);
        float f = baff[o] + s.x + s.y;
        float Av = 1.f / (1.f + __expf(-f));
        g_Amat[(k * PP + o) * PP + j] = Av;
        deg += Av;
    }
    g_dis[k * PP + j] = rsqrtf(deg);
}

// ---------------- y1 = dis_i * (X @ W1) ----------------------------------------
__global__ void __launch_bounds__(PP) k_y1(const float* __restrict__ rf,
                                           const float* __restrict__ w1) {
    __shared__ float s_w1[CC * G16];
    int k = blockIdx.x;
    int i = threadIdx.x;
    for (int t = i; t < CC * G16; t += PP) s_w1[t] = w1[t];
    __syncthreads();
    u64 acc[8];
    #pragma unroll
    for (int g = 0; g < 8; g++) acc[g] = 0ull;
    for (int f = 0; f < CC; f++) {
        float xv = rf[(k * CC + f) * PP + i];
        u64 x2 = pack2(xv, xv);
        const u64* wr = (const u64*)(s_w1 + f * G16);
        #pragma unroll
        for (int g = 0; g < 8; g++) acc[g] = ffma2(x2, wr[g], acc[g]);
    }
    float d = g_dis[k * PP + i];
    float* op = g_y1 + (k * PP + i) * G16;
    #pragma unroll
    for (int g = 0; g < 8; g++) {
        float2 v = unpack2(acc[g]);
        op[2 * g] = d * v.x; op[2 * g + 1] = d * v.y;
    }
}

// ---------------- x1' = dis_j * relu(dis_j * (A^T y1) + b1) --------------------
__global__ void __launch_bounds__(PP) k_x1(const float* __restrict__ b1) {
    __shared__ float s_y[PP * G16];
    int k = blockIdx.x;
    int j = threadIdx.x;
    for (int t = j; t < PP * G16; t += PP) s_y[t] = g_y1[k * PP * G16 + t];
    __syncthreads();
    u64 acc[8];
    #pragma unroll
    for (int g = 0; g < 8; g++) acc[g] = 0ull;
    for (int i = 0; i < PP; i++) {
        float a = g_Amat[(k * PP + i) * PP + j];
        u64 a2 = pack2(a, a);
        const u64* yr = (const u64*)(s_y + i * G16);
        #pragma unroll
        for (int g = 0; g < 8; g++) acc[g] = ffma2(a2, yr[g], acc[g]);
    }
    float d = g_dis[k * PP + j];
    float* op = g_x1 + (k * PP + j) * G16;
    #pragma unroll
    for (int g = 0; g < 8; g++) {
        float2 v = unpack2(acc[g]);
        op[2 * g]     = d * fmaxf(d * v.x + b1[2 * g], 0.f);
        op[2 * g + 1] = d * fmaxf(d * v.y + b1[2 * g + 1], 0.f);
    }
}

// ---------------- agg2 + final add ---------------------------------------------
#define ZSTRIDE 68
__global__ void __launch_bounds__(PP) k_agg2(const float* __restrict__ w2,
                                             const float* __restrict__ b2,
                                             float* __restrict__ out) {
    extern __shared__ float smdyn[];
    float* s_x = smdyn;                    // [196][16]
    float* s_w2 = smdyn + PP * G16;        // [16][64]
    float* s_Z = s_w2 + G16 * 64;          // [196][68]
    int k = blockIdx.x;
    int c0 = blockIdx.y * 64;
    int j = threadIdx.x;

    for (int t = j; t < PP * G16; t += PP) s_x[t] = g_x1[k * PP * G16 + t];
    for (int t = j; t < G16 * 64; t += PP) {
        int g = t / 64, c = t % 64;
        s_w2[t] = w2[g * CC + c0 + c];
    }
    __syncthreads();

    {   // phase 1: Z[i, c-tile] = x1'[i,:] @ W2[:, c-tile]
        const float* xr = s_x + j * G16;
        float xv[G16];
        #pragma unroll
        for (int g = 0; g < G16; g++) xv[g] = xr[g];
        #pragma unroll 4
        for (int c = 0; c < 64; c++) {
            float t = 0.f;
            #pragma unroll
            for (int g = 0; g < G16; g++) t += xv[g] * s_w2[g * 64 + c];
            s_Z[j * ZSTRIDE + c] = t;
        }
    }
    __syncthreads();

    u64 acc[32];
    #pragma unroll
    for (int c = 0; c < 32; c++) acc[c] = 0ull;
    for (int i = 0; i < PP; i++) {
        float a = g_Amat[(k * PP + i) * PP + j];
        u64 a2 = pack2(a, a);
        const u64* zr = (const u64*)(s_Z + i * ZSTRIDE);
        #pragma unroll
        for (int c = 0; c < 32; c++) acc[c] = ffma2(a2, zr[c], acc[c]);
    }
    float d = g_dis[k * PP + j];
    #pragma unroll
    for (int c = 0; c < 32; c++) {
        float2 v = unpack2(acc[c]);
        int cg0 = c0 + 2 * c;
        int idx0 = (k * CC + cg0) * PP + j;
        out[idx0]      = g_roi_sem[idx0] + b2[cg0] + d * v.x;
        out[idx0 + PP] = g_roi_sem[idx0 + PP] + b2[cg0 + 1] + d * v.y;
    }
}

// ---------------- launch --------------------------------------------------------
extern "C" void kernel_launch(void* const* d_in, const int* in_sizes, int n_in,
                              void* d_out, int out_size) {
    const float* roi_feature = (const float*)d_in[0];
    const float* semantic    = (const float*)d_in[1];
    const float* boxes       = (const float*)d_in[2];
    const float* bn_sem_g = (const float*)d_in[3];
    const float* bn_sem_b = (const float*)d_in[4];
    const float* bn_sem_m = (const float*)d_in[5];
    const float* bn_sem_v = (const float*)d_in[6];
    const float* conv_sem_w = (const float*)d_in[7];
    const float* conv_sem_b = (const float*)d_in[8];
    const float* bn_fpn_g = (const float*)d_in[9];
    const float* bn_fpn_b = (const float*)d_in[10];
    const float* bn_fpn_m = (const float*)d_in[11];
    const float* bn_fpn_v = (const float*)d_in[12];
    const float* conv_fpn_w = (const float*)d_in[13];
    const float* conv_fpn_b = (const float*)d_in[14];
    const float* bn_aff_g = (const float*)d_in[15];
    const float* bn_aff_b = (const float*)d_in[16];
    const float* bn_aff_m = (const float*)d_in[17];
    const float* bn_aff_v = (const float*)d_in[18];
    const float* conv_aff_w = (const float*)d_in[19];
    const float* conv_aff_b = (const float*)d_in[20];
    const float* gcn1_w = (const float*)d_in[21];
    const float* gcn1_b = (const float*)d_in[22];
    const float* gcn2_w = (const float*)d_in[23];
    const float* gcn2_b = (const float*)d_in[24];
    float* out = (float*)d_out;

    static int attr_done = 0;
    if (!attr_done) {
        cudaFuncSetAttribute(k_roi, cudaFuncAttributeMaxDynamicSharedMemorySize,
                             ROI_SMEM);
        cudaFuncSetAttribute(k_aff, cudaFuncAttributeMaxDynamicSharedMemorySize,
                             PP * OC64 * 4);
        cudaFuncSetAttribute(k_agg2, cudaFuncAttributeMaxDynamicSharedMemorySize,
                             (PP * G16 + G16 * 64 + PP * ZSTRIDE) * 4);
        attr_done = 1;
    }

    k_bnprep<<<1, 256>>>(bn_sem_g, bn_sem_b, bn_sem_m, bn_sem_v,
                         bn_fpn_g, bn_fpn_b, bn_fpn_m, bn_fpn_v,
                         bn_aff_g, bn_aff_b, bn_aff_m, bn_aff_v);
    k_wpack<<<(2 * CC * 32 * 9 + 255) / 256, 256>>>(conv_sem_w, conv_fpn_w);
    k_transpose<<<dim3(CC / 32, HWSZ / 32, BB), dim3(32, 8)>>>(semantic);
    {
        int n4 = KK * CC * (PP / 4);
        k_actfpn<<<(n4 + 255) / 256, 256>>>(roi_feature);
    }
    k_roi<<<KK, 256, ROI_SMEM>>>(boxes);
    k_conv<<<dim3(KK, 2), PP>>>(conv_sem_b, conv_fpn_b);
    k_aff<<<KK, PP, PP * OC64 * 4>>>(conv_aff_w, conv_aff_b);
    k_y1<<<KK, PP>>>(roi_feature, gcn1_w);
    k_x1<<<KK, PP>>>(gcn1_b);
    k_agg2<<<dim3(KK, CC / 64), PP, (PP * G16 + G16 * 64 + PP * ZSTRIDE) * 4>>>(
        gcn2_w, gcn2_b, out);
}